// round 14
// baseline (speedup 1.0000x reference)
#include <cuda_runtime.h>
#include <cuda_bf16.h>
#include <cstdint>

#define NB 64
#define NN 256
#define INF_F 1e30f
#define FULLM 0xFFFFFFFFu
#define RROWS 220                       // cost rows staged in shared memory
#define SMEM_BYTES (RROWS * NN * 4 + 5 * NN * 4)   // 230400 B <= 227 KB

// Transposed cost matrices: g_cmat[b][i][j] = costs[b][j][i]
__device__ float g_cmat[NB * NN * NN];

// Monotonic float->uint order encoding (injective; preserves < and ==)
__device__ __forceinline__ unsigned enc_f(float x) {
    const unsigned b = __float_as_uint(x);
    return b ^ (unsigned)(((int)b >> 31) | 0x80000000);
}
__device__ __forceinline__ float dec_f(unsigned e) {
    const unsigned b = (e & 0x80000000u) ? (e ^ 0x80000000u) : ~e;
    return __uint_as_float(b);
}

// ---------------------------------------------------------------------------
// Kernel 1: tiled transpose with inline costs-dtype detection (f32 vs bf16).
// ---------------------------------------------------------------------------
__global__ void transpose_kernel(const void* __restrict__ in) {
    const __nv_bfloat16* hb = (const __nv_bfloat16*)in;
    bool isbf = true;
    float acc = 0.0f;
    #pragma unroll
    for (int k = 0; k < 64; k++) {
        const float x = __bfloat162float(hb[k]);
        if (!isfinite(x) || fabsf(x) > 1e4f) isbf = false;
        else acc += x * x;
    }
    const float ms = acc * (1.0f / 64.0f);
    if (ms < 0.05f || ms > 20.0f) isbf = false;

    __shared__ float t[32][33];
    const int b  = blockIdx.z;
    const int j0 = blockIdx.x * 32;
    const int i0 = blockIdx.y * 32;
    float* dst = g_cmat + (size_t)b * NN * NN;
    const int tx = threadIdx.x, ty = threadIdx.y;
    if (isbf) {
        const __nv_bfloat16* src = (const __nv_bfloat16*)in + (size_t)b * NN * NN;
        #pragma unroll
        for (int r = ty; r < 32; r += 8)
            t[r][tx] = __bfloat162float(src[(j0 + r) * NN + i0 + tx]);
    } else {
        const float* src = (const float*)in + (size_t)b * NN * NN;
        #pragma unroll
        for (int r = ty; r < 32; r += 8)
            t[r][tx] = src[(j0 + r) * NN + i0 + tx];
    }
    __syncthreads();
    #pragma unroll
    for (int r = ty; r < 32; r += 8)
        dst[(i0 + r) * NN + j0 + tx] = t[tx][r];
}

// ---------------------------------------------------------------------------
// Kernel 2: one warp per batch, valid-rows-only Jonker-Volgenant with the
// reference-identical trajectory (v=0 init, rows in order, same FP op order,
// first-index argmin tie-break). Lane owns PAIRED columns
// {k*64 + 2*lane + m : k<4, m<2} (slot kk = 2k+m) so row reads are 4x LDS.64.
// SC columns are excluded from relax by vm[kk] = -INF (rr becomes ~1e30,
// encoded above every finite sp) instead of a SEL on the critical chain.
// ---------------------------------------------------------------------------
__global__ void __launch_bounds__(32, 1) lap_kernel(const void* __restrict__ mask,
                                                    float* __restrict__ out) {
    extern __shared__ unsigned char s_raw[];
    float* s_cost = (float*)s_raw;                       // [RROWS][NN]
    float* s_u    = (float*)(s_raw + RROWS * NN * 4);
    float* s_sp   = s_u + NN;
    int*   s_path = (int*)(s_sp + NN);
    int*   s_c4r  = s_path + NN;
    int*   s_r4c  = s_c4r + NN;

    const int b    = blockIdx.x;
    const int lane = threadIdx.x;
    const float* __restrict__ C = g_cmat + (size_t)b * NN * NN;

    // column owned at slot kk (kk = 2k+m)
    #define COLOF(kk) (((kk) >> 1) * 64 + 2 * lane + ((kk) & 1))

    // ---- nv from mask (byte / int32 / float32 bools; elem 0 always true) ---
    const unsigned w0 = *(const unsigned*)mask;
    const bool wide = (w0 == 1u) || (w0 == 0x3f800000u);
    int nz = 0;
    if (wide) {
        const unsigned* m = (const unsigned*)mask + b * NN;
        #pragma unroll
        for (int k = 0; k < 8; k++) nz += (m[k * 32 + lane] != 0u) ? 1 : 0;
    } else {
        const unsigned char* m = (const unsigned char*)mask + b * NN;
        #pragma unroll
        for (int k = 0; k < 8; k++) nz += (m[k * 32 + lane] != 0) ? 1 : 0;
    }
    const int nv = __reduce_add_sync(FULLM, nz);

    // ---- stage cost rows [0, min(nv,RROWS)) into shared memory ----
    {
        const int nrow = (nv < RROWS) ? nv : RROWS;
        const int nvec = nrow * (NN / 4);
        const float4* __restrict__ src = (const float4*)C;
        float4* dst = (float4*)s_cost;
        for (int t = lane; t < nvec; t += 32) dst[t] = src[t];
    }

    const unsigned ENC_INF = enc_f(INF_F);
    const float NEG_INF = -INF_F;

    // ---- init ----
    float v[8], vm[8];
    unsigned spv[8], spm[8];
    int path[8], r4cr[8];
    #pragma unroll
    for (int k = 0; k < 8; k++) {
        const int idx = k * 32 + lane;   // any full cover is fine for init
        v[k] = 0.0f;
        path[k] = -1;
        s_u[idx] = 0.0f;
        s_c4r[idx] = -1;
        s_r4c[idx] = -1;
        out[b * NN + idx] = (float)idx;  // defensive pre-fill
    }
    __syncwarp();

    for (int cur = 0; cur < nv; cur++) {
        unsigned SC  = 0;
        unsigned SRm = (((cur >> 1) & 31) == lane)
                     ? (1u << ((((unsigned)cur >> 6) << 1) | (cur & 1))) : 0u;
        #pragma unroll
        for (int k = 0; k < 8; k++) {
            spv[k] = ENC_INF;
            spm[k] = ENC_INF;
            vm[k]  = v[k];
            r4cr[k] = s_r4c[COLOF(k)];   // snapshot (constant this run)
        }

        int   i  = cur;
        float mv = 0.0f;                 // minVal
        int   sink;

        // ---------------- Dijkstra ----------------
        for (;;) {
            const float ucur = s_u[i];
            float2 cv2[4];
            if (i < RROWS) {
                const float2* __restrict__ r2 =
                    (const float2*)s_cost + i * 128 + lane;
                #pragma unroll
                for (int k = 0; k < 4; k++) cv2[k] = r2[k * 32];
            } else {
                const float2* __restrict__ r2 =
                    (const float2*)C + i * 128 + lane;
                #pragma unroll
                for (int k = 0; k < 4; k++) cv2[k] = __ldg(r2 + k * 32);
            }
            float cv[8];
            #pragma unroll
            for (int k = 0; k < 4; k++) {
                cv[2 * k]     = cv2[k].x;
                cv[2 * k + 1] = cv2[k].y;
            }

            // relax (reference FP order): rr = ((mv + c) - u[i]) - vm[k].
            // SC columns have vm = -INF -> rr = ~1e30 -> never wins/updates.
            #pragma unroll
            for (int k = 0; k < 8; k++) {
                const float rr = ((mv + cv[k]) - ucur) - vm[k];
                const unsigned e = enc_f(rr);
                if (e < spv[k]) path[k] = i;      // off-chain bookkeeping
                spv[k] = min(spv[k], e);
                spm[k] = min(spm[k], e);
            }

            // local min via integer min tree
            const unsigned m01 = min(spm[0], spm[1]);
            const unsigned m23 = min(spm[2], spm[3]);
            const unsigned m45 = min(spm[4], spm[5]);
            const unsigned m67 = min(spm[6], spm[7]);
            const unsigned mloc = min(min(m01, m23), min(m45, m67));

            const unsigned mOrd = __reduce_min_sync(FULLM, mloc);

            // off-chain: lowest-kk tied slot (monotone in column) + row4col
            unsigned bits = 0;
            #pragma unroll
            for (int k = 0; k < 8; k++)
                if (spm[k] == mloc) bits |= 1u << k;
            const unsigned oneh = bits & (unsigned)(-(int)bits);
            int nxtl1 = 0;
            #pragma unroll
            for (int k = 0; k < 8; k++)
                nxtl1 += (int)((oneh >> k) & 1u) * (r4cr[k] + 1);
            const int kf = __ffs(bits) - 1;
            const unsigned bestIdx = (unsigned)COLOF(kf);

            // packed candidate: [col:8][row4col+1:9]; REDUX-min = exact
            // lowest-global-index tie-break; winner carries next row free
            const unsigned cand = (mloc == mOrd)
                                ? ((bestIdx << 9) | (unsigned)nxtl1)
                                : 0x7FFFFFFFu;
            const unsigned cw = __reduce_min_sync(FULLM, cand);
            const int jmin = (int)(cw >> 9);
            const int nxt  = (int)(cw & 511u) - 1;

            mv = dec_f(mOrd);            // hides under REDUX2

            if (((jmin >> 1) & 31) == lane) {
                const int kk = (((unsigned)jmin >> 6) << 1) | (jmin & 1);
                SC |= 1u << kk;
                spm[kk] = 0xFFFFFFFFu;   // spv[kk] stays frozen (true value)
                vm[kk]  = NEG_INF;       // excludes column from future relax
            }
            if (nxt < 0) { sink = jmin; break; }
            i = nxt;
            if (((nxt >> 1) & 31) == lane)
                SRm |= 1u << ((((unsigned)nxt >> 6) << 1) | (nxt & 1));
        }

        // write back sp (decoded) + path for the random-access phases
        float sp[8];
        #pragma unroll
        for (int k = 0; k < 8; k++) {
            const int idx = COLOF(k);
            sp[k] = dec_f(spv[k]);
            s_sp[idx]   = sp[k];
            s_path[idx] = path[k];
            path[k] = -1;
        }
        __syncwarp();

        // ---------------- dual potential updates ----------------
        #pragma unroll
        for (int k = 0; k < 8; k++) {
            const int rrow = COLOF(k);
            if ((SRm >> k) & 1u) {
                int cc = s_c4r[rrow];
                cc = (cc < 0) ? 0 : ((cc > NN - 1) ? NN - 1 : cc);  // ref clip
                const float du = (rrow == cur) ? mv : (mv - s_sp[cc]);
                s_u[rrow] += du;
            }
            if ((SC >> k) & 1u) v[k] -= (mv - sp[k]);
        }
        __syncwarp();

        // ---------------- augment along alternating path ----------------
        if (lane == 0) {
            int j = sink;
            for (;;) {
                const int pi = s_path[j];
                s_r4c[j] = pi;
                const int jn = s_c4r[pi];
                s_c4r[pi] = j;
                if (pi == cur) break;
                j = jn;
            }
        }
        __syncwarp();
    }

    // ---------------- write output (float32 values) ----------------
    #pragma unroll
    for (int k = 0; k < 8; k++) {
        const int r = COLOF(k);
        if (r < nv) {
            int c = s_c4r[r];
            c = (c < 0) ? 0 : ((c > NN - 1) ? NN - 1 : c);
            out[b * NN + r] = (float)c;
        }
    }
    __syncwarp();
    if (lane == 0) {
        int pos = nv;
        for (int j = 0; j < NN; j++) {
            if (s_r4c[j] < 0 && pos < NN) out[b * NN + pos++] = (float)j;
        }
    }
    #undef COLOF
}

// ---------------------------------------------------------------------------
extern "C" void kernel_launch(void* const* d_in, const int* in_sizes, int n_in,
                              void* d_out, int out_size) {
    const void* costs = d_in[0];
    const void* mask  = (n_in > 1) ? d_in[1] : d_in[0];
    for (int i = 0; i < n_in; i++) {
        if (in_sizes[i] == NB * NN * NN) costs = d_in[i];
        else if (in_sizes[i] == NB * NN) mask = d_in[i];
    }
    float* out = (float*)d_out;

    cudaFuncSetAttribute(lap_kernel,
                         cudaFuncAttributeMaxDynamicSharedMemorySize,
                         SMEM_BYTES);

    transpose_kernel<<<dim3(NN / 32, NN / 32, NB), dim3(32, 8)>>>(costs);
    lap_kernel<<<NB, 32, SMEM_BYTES>>>(mask, out);
}

// round 15
// speedup vs baseline: 1.0900x; 1.0900x over previous
#include <cuda_runtime.h>
#include <cuda_bf16.h>
#include <cstdint>

#define NB 64
#define NN 256
#define INF_F 1e30f
#define FULLM 0xFFFFFFFFu
#define RROWS 220                       // cost rows staged in shared memory
#define SMEM_BYTES (RROWS * NN * 4 + 5 * NN * 4)   // 230400 B <= 227 KB

// Transposed cost matrices: g_cmat[b][i][j] = costs[b][j][i]
__device__ float g_cmat[NB * NN * NN];

// Monotonic float->uint order encoding (injective; preserves < and ==)
__device__ __forceinline__ unsigned enc_f(float x) {
    const unsigned b = __float_as_uint(x);
    return b ^ (unsigned)(((int)b >> 31) | 0x80000000);
}
__device__ __forceinline__ float dec_f(unsigned e) {
    const unsigned b = (e & 0x80000000u) ? (e ^ 0x80000000u) : ~e;
    return __uint_as_float(b);
}

// ---------------------------------------------------------------------------
// Kernel 1: tiled transpose with inline costs-dtype detection (f32 vs bf16).
// ---------------------------------------------------------------------------
__global__ void transpose_kernel(const void* __restrict__ in) {
    const __nv_bfloat16* hb = (const __nv_bfloat16*)in;
    bool isbf = true;
    float acc = 0.0f;
    #pragma unroll
    for (int k = 0; k < 64; k++) {
        const float x = __bfloat162float(hb[k]);
        if (!isfinite(x) || fabsf(x) > 1e4f) isbf = false;
        else acc += x * x;
    }
    const float ms = acc * (1.0f / 64.0f);
    if (ms < 0.05f || ms > 20.0f) isbf = false;

    __shared__ float t[32][33];
    const int b  = blockIdx.z;
    const int j0 = blockIdx.x * 32;
    const int i0 = blockIdx.y * 32;
    float* dst = g_cmat + (size_t)b * NN * NN;
    const int tx = threadIdx.x, ty = threadIdx.y;
    if (isbf) {
        const __nv_bfloat16* src = (const __nv_bfloat16*)in + (size_t)b * NN * NN;
        #pragma unroll
        for (int r = ty; r < 32; r += 8)
            t[r][tx] = __bfloat162float(src[(j0 + r) * NN + i0 + tx]);
    } else {
        const float* src = (const float*)in + (size_t)b * NN * NN;
        #pragma unroll
        for (int r = ty; r < 32; r += 8)
            t[r][tx] = src[(j0 + r) * NN + i0 + tx];
    }
    __syncthreads();
    #pragma unroll
    for (int r = ty; r < 32; r += 8)
        dst[(i0 + r) * NN + j0 + tx] = t[tx][r];
}

// ---------------------------------------------------------------------------
// Kernel 2: one warp per batch, valid-rows-only Jonker-Volgenant with the
// reference-identical trajectory (v=0 init, rows in order, same FP op order,
// first-index argmin tie-break). IDENTICAL to the measured-best round-13
// kernel except ONE change: the smem cost tile is stored permuted+swizzled
// so lane L's columns {k*32+L} sit contiguously at 8L + (k ^ 4*((L>>2)&1)),
// making the row read 2x conflict-free LDS.128 instead of 8 scalar LDS.
// Control arrays keep the strided {k*32+lane} indexing (conflict-free).
// ---------------------------------------------------------------------------
__global__ void __launch_bounds__(32, 1) lap_kernel(const void* __restrict__ mask,
                                                    float* __restrict__ out) {
    extern __shared__ unsigned char s_raw[];
    float* s_cost = (float*)s_raw;                       // [RROWS][NN] permuted
    float* s_u    = (float*)(s_raw + RROWS * NN * 4);
    float* s_sp   = s_u + NN;
    int*   s_path = (int*)(s_sp + NN);
    int*   s_c4r  = s_path + NN;
    int*   s_r4c  = s_c4r + NN;

    const int b    = blockIdx.x;
    const int lane = threadIdx.x;
    const float* __restrict__ C = g_cmat + (size_t)b * NN * NN;

    // ---- nv from mask (byte / int32 / float32 bools; elem 0 always true) ---
    const unsigned w0 = *(const unsigned*)mask;
    const bool wide = (w0 == 1u) || (w0 == 0x3f800000u);
    int nz = 0;
    if (wide) {
        const unsigned* m = (const unsigned*)mask + b * NN;
        #pragma unroll
        for (int k = 0; k < 8; k++) nz += (m[k * 32 + lane] != 0u) ? 1 : 0;
    } else {
        const unsigned char* m = (const unsigned char*)mask + b * NN;
        #pragma unroll
        for (int k = 0; k < 8; k++) nz += (m[k * 32 + lane] != 0) ? 1 : 0;
    }
    const int nv = __reduce_add_sync(FULLM, nz);

    // ---- stage cost rows [0, min(nv,RROWS)) into permuted smem layout:
    // col -> 8*(col&31) + ((col>>5) ^ (4*(((col&31)>>2)&1)))
    {
        const int nrow = (nv < RROWS) ? nv : RROWS;
        const int nvec = nrow * (NN / 4);
        const float4* __restrict__ src = (const float4*)C;
        for (int t = lane; t < nvec; t += 32) {
            const float4 val = src[t];
            const int row  = t >> 6;
            const int col0 = (t & 63) * 4;
            float* drow = s_cost + row * NN;
            #pragma unroll
            for (int m = 0; m < 4; m++) {
                const int col = col0 + m;
                const int k = col >> 5, L = col & 31;
                const int sw = ((L >> 2) & 1) << 2;
                drow[8 * L + (k ^ sw)] = (&val.x)[m];
            }
        }
    }

    const unsigned ENC_INF = enc_f(INF_F);
    // per-lane row-read pointers (uniform per lane; chunk A = k0..3, B = k4..7)
    const int sL  = (lane >> 2) & 1;
    const int offA = 8 * lane + 4 * sL;
    const int offB = 8 * lane + 4 - 4 * sL;

    // ---- init (lane owns columns/rows {k*32+lane}) ----
    float v[8];
    unsigned spv[8], spm[8];
    int path[8], r4cr[8];
    #pragma unroll
    for (int k = 0; k < 8; k++) {
        const int idx = k * 32 + lane;
        v[k] = 0.0f;
        path[k] = -1;
        s_u[idx] = 0.0f;
        s_c4r[idx] = -1;
        s_r4c[idx] = -1;
        out[b * NN + idx] = (float)idx;  // defensive pre-fill
    }
    __syncwarp();

    for (int cur = 0; cur < nv; cur++) {
        unsigned SC  = 0;
        unsigned SRm = ((cur & 31) == lane) ? (1u << (cur >> 5)) : 0u;
        #pragma unroll
        for (int k = 0; k < 8; k++) {
            spv[k] = ENC_INF;
            spm[k] = ENC_INF;
            r4cr[k] = s_r4c[k * 32 + lane];   // snapshot (constant this run)
        }

        int   i  = cur;
        float mv = 0.0f;                 // minVal
        int   sink;

        // ---------------- Dijkstra ----------------
        for (;;) {
            const float ucur = s_u[i];
            float cv[8];
            if (i < RROWS) {
                const float4 a  = *(const float4*)(s_cost + i * NN + offA);
                const float4 bq = *(const float4*)(s_cost + i * NN + offB);
                cv[0] = a.x;  cv[1] = a.y;  cv[2] = a.z;  cv[3] = a.w;
                cv[4] = bq.x; cv[5] = bq.y; cv[6] = bq.z; cv[7] = bq.w;
            } else {
                const float* __restrict__ r = C + i * NN;
                #pragma unroll
                for (int k = 0; k < 8; k++) cv[k] = __ldg(r + k * 32 + lane);
            }

            // relax (reference FP order) in encoded domain, unpredicated:
            // em = SC ? UMAX : enc(rr); spv/spm via IMNMX (no pred on chain).
            #pragma unroll
            for (int k = 0; k < 8; k++) {
                const float rr = ((mv + cv[k]) - ucur) - v[k];
                const unsigned e  = enc_f(rr);
                const unsigned em = ((SC >> k) & 1u) ? 0xFFFFFFFFu : e;
                if (em < spv[k]) path[k] = i;     // off-chain bookkeeping
                spv[k] = min(spv[k], em);
                spm[k] = min(spm[k], em);
            }

            // local min via integer min tree (order-isomorphic to float min)
            const unsigned m01 = min(spm[0], spm[1]);
            const unsigned m23 = min(spm[2], spm[3]);
            const unsigned m45 = min(spm[4], spm[5]);
            const unsigned m67 = min(spm[6], spm[7]);
            const unsigned mloc = min(min(m01, m23), min(m45, m67));

            const unsigned mOrd = __reduce_min_sync(FULLM, mloc);

            // off-chain: lowest-k tied index + its row4col
            unsigned bits = 0;
            #pragma unroll
            for (int k = 0; k < 8; k++)
                if (spm[k] == mloc) bits |= 1u << k;
            const unsigned oneh = bits & (unsigned)(-(int)bits);
            int nxtl1 = 0;
            #pragma unroll
            for (int k = 0; k < 8; k++)
                nxtl1 += (int)((oneh >> k) & 1u) * (r4cr[k] + 1);
            const int kf = __ffs(bits) - 1;
            const unsigned bestIdx = (unsigned)(kf * 32 + lane);

            // packed candidate: [idx:8][row4col+1:9]; REDUX-min = exact
            // lowest-global-index tie-break; winner carries next row free
            const unsigned cand = (mloc == mOrd)
                                ? ((bestIdx << 9) | (unsigned)nxtl1)
                                : 0x7FFFFFFFu;
            const unsigned cw = __reduce_min_sync(FULLM, cand);
            const int jmin = (int)(cw >> 9);
            const int nxt  = (int)(cw & 511u) - 1;

            mv = dec_f(mOrd);            // hides under REDUX2

            if ((jmin & 31) == lane) {
                const int kk = jmin >> 5;
                SC |= 1u << kk;
                spm[kk] = 0xFFFFFFFFu;   // spv[kk] stays frozen (true value)
            }
            if (nxt < 0) { sink = jmin; break; }
            i = nxt;
            if ((nxt & 31) == lane) SRm |= 1u << (nxt >> 5);
        }

        // write back sp (decoded) + path for the random-access phases
        float sp[8];
        #pragma unroll
        for (int k = 0; k < 8; k++) {
            const int idx = k * 32 + lane;
            sp[k] = dec_f(spv[k]);
            s_sp[idx]   = sp[k];
            s_path[idx] = path[k];
        }
        __syncwarp();

        // ---------------- dual potential updates ----------------
        #pragma unroll
        for (int k = 0; k < 8; k++) {
            const int rrow = k * 32 + lane;
            if ((SRm >> k) & 1u) {
                int cc = s_c4r[rrow];
                cc = (cc < 0) ? 0 : ((cc > NN - 1) ? NN - 1 : cc);  // ref clip
                const float du = (rrow == cur) ? mv : (mv - s_sp[cc]);
                s_u[rrow] += du;
            }
            if ((SC >> k) & 1u) v[k] -= (mv - sp[k]);
        }
        __syncwarp();

        // ---------------- augment along alternating path ----------------
        if (lane == 0) {
            int j = sink;
            for (;;) {
                const int pi = s_path[j];
                s_r4c[j] = pi;
                const int jn = s_c4r[pi];
                s_c4r[pi] = j;
                if (pi == cur) break;
                j = jn;
            }
        }
        __syncwarp();
    }

    // ---------------- write output (float32 values) ----------------
    #pragma unroll
    for (int k = 0; k < 8; k++) {
        const int r = k * 32 + lane;
        if (r < nv) {
            int c = s_c4r[r];
            c = (c < 0) ? 0 : ((c > NN - 1) ? NN - 1 : c);
            out[b * NN + r] = (float)c;
        }
    }
    __syncwarp();
    if (lane == 0) {
        int pos = nv;
        for (int j = 0; j < NN; j++) {
            if (s_r4c[j] < 0 && pos < NN) out[b * NN + pos++] = (float)j;
        }
    }
}

// ---------------------------------------------------------------------------
extern "C" void kernel_launch(void* const* d_in, const int* in_sizes, int n_in,
                              void* d_out, int out_size) {
    const void* costs = d_in[0];
    const void* mask  = (n_in > 1) ? d_in[1] : d_in[0];
    for (int i = 0; i < n_in; i++) {
        if (in_sizes[i] == NB * NN * NN) costs = d_in[i];
        else if (in_sizes[i] == NB * NN) mask = d_in[i];
    }
    float* out = (float*)d_out;

    cudaFuncSetAttribute(lap_kernel,
                         cudaFuncAttributeMaxDynamicSharedMemorySize,
                         SMEM_BYTES);

    transpose_kernel<<<dim3(NN / 32, NN / 32, NB), dim3(32, 8)>>>(costs);
    lap_kernel<<<NB, 32, SMEM_BYTES>>>(mask, out);
}

// round 17
// speedup vs baseline: 1.2574x; 1.1535x over previous
#include <cuda_runtime.h>
#include <cuda_bf16.h>
#include <cstdint>

#define NB 64
#define NN 256
#define INF_F 1e30f
#define FULLM 0xFFFFFFFFu
#define RROWS 220                       // cost rows staged in shared memory
#define SMEM_BYTES (RROWS * NN * 4 + 5 * NN * 4)   // 230400 B <= 227 KB

// Transposed cost matrices: g_cmat[b][i][j] = costs[b][j][i]
__device__ float g_cmat[NB * NN * NN];

// Monotonic float->uint order encoding (injective; preserves < and ==)
__device__ __forceinline__ unsigned enc_f(float x) {
    const unsigned b = __float_as_uint(x);
    return b ^ (unsigned)(((int)b >> 31) | 0x80000000);
}
__device__ __forceinline__ float dec_f(unsigned e) {
    const unsigned b = (e & 0x80000000u) ? (e ^ 0x80000000u) : ~e;
    return __uint_as_float(b);
}

// ---------------------------------------------------------------------------
// Kernel 1: tiled transpose with inline costs-dtype detection (f32 vs bf16).
// ---------------------------------------------------------------------------
__global__ void transpose_kernel(const void* __restrict__ in) {
    const __nv_bfloat16* hb = (const __nv_bfloat16*)in;
    bool isbf = true;
    float acc = 0.0f;
    #pragma unroll
    for (int k = 0; k < 64; k++) {
        const float x = __bfloat162float(hb[k]);
        if (!isfinite(x) || fabsf(x) > 1e4f) isbf = false;
        else acc += x * x;
    }
    const float ms = acc * (1.0f / 64.0f);
    if (ms < 0.05f || ms > 20.0f) isbf = false;

    __shared__ float t[32][33];
    const int b  = blockIdx.z;
    const int j0 = blockIdx.x * 32;
    const int i0 = blockIdx.y * 32;
    float* dst = g_cmat + (size_t)b * NN * NN;
    const int tx = threadIdx.x, ty = threadIdx.y;
    if (isbf) {
        const __nv_bfloat16* src = (const __nv_bfloat16*)in + (size_t)b * NN * NN;
        #pragma unroll
        for (int r = ty; r < 32; r += 8)
            t[r][tx] = __bfloat162float(src[(j0 + r) * NN + i0 + tx]);
    } else {
        const float* src = (const float*)in + (size_t)b * NN * NN;
        #pragma unroll
        for (int r = ty; r < 32; r += 8)
            t[r][tx] = src[(j0 + r) * NN + i0 + tx];
    }
    __syncthreads();
    #pragma unroll
    for (int r = ty; r < 32; r += 8)
        dst[(i0 + r) * NN + j0 + tx] = t[tx][r];
}

// ---------------------------------------------------------------------------
// Kernel 2: one warp per batch, valid-rows-only Jonker-Volgenant with the
// reference-identical trajectory (v=0 init, rows in order, same FP op order,
// first-index argmin tie-break). Round-13 base (measured best load pattern:
// 8 scalar LDS, strided {k*32+lane} ownership). Deltas vs r13:
//  (a) branchless candidate select between the two REDUXes;
//  (b) spv shadow removed — frozen sp of an SC column equals the mv at its
//      SC-entry (jmin is the argmin), recorded in scv[] instead.
// ---------------------------------------------------------------------------
__global__ void __launch_bounds__(32, 1) lap_kernel(const void* __restrict__ mask,
                                                    float* __restrict__ out) {
    extern __shared__ unsigned char s_raw[];
    float* s_cost = (float*)s_raw;                       // [RROWS][NN]
    float* s_u    = (float*)(s_raw + RROWS * NN * 4);
    float* s_sp   = s_u + NN;
    int*   s_path = (int*)(s_sp + NN);
    int*   s_c4r  = s_path + NN;
    int*   s_r4c  = s_c4r + NN;

    const int b    = blockIdx.x;
    const int lane = threadIdx.x;
    const float* __restrict__ C = g_cmat + (size_t)b * NN * NN;

    // ---- nv from mask (byte / int32 / float32 bools; elem 0 always true) ---
    const unsigned w0 = *(const unsigned*)mask;
    const bool wide = (w0 == 1u) || (w0 == 0x3f800000u);
    int nz = 0;
    if (wide) {
        const unsigned* m = (const unsigned*)mask + b * NN;
        #pragma unroll
        for (int k = 0; k < 8; k++) nz += (m[k * 32 + lane] != 0u) ? 1 : 0;
    } else {
        const unsigned char* m = (const unsigned char*)mask + b * NN;
        #pragma unroll
        for (int k = 0; k < 8; k++) nz += (m[k * 32 + lane] != 0) ? 1 : 0;
    }
    const int nv = __reduce_add_sync(FULLM, nz);

    // ---- stage cost rows [0, min(nv,RROWS)) into shared memory ----
    {
        const int nrow = (nv < RROWS) ? nv : RROWS;
        const int nvec = nrow * (NN / 4);
        const float4* __restrict__ src = (const float4*)C;
        float4* dst = (float4*)s_cost;
        for (int t = lane; t < nvec; t += 32) dst[t] = src[t];
    }

    const unsigned ENC_INF = enc_f(INF_F);

    // ---- init (lane owns columns/rows {k*32+lane}) ----
    float v[8], scv[8];
    unsigned spm[8];
    int path[8], r4cr[8];
    #pragma unroll
    for (int k = 0; k < 8; k++) {
        const int idx = k * 32 + lane;
        v[k] = 0.0f;
        path[k] = -1;
        s_u[idx] = 0.0f;
        s_c4r[idx] = -1;
        s_r4c[idx] = -1;
        out[b * NN + idx] = (float)idx;  // defensive pre-fill
    }
    __syncwarp();

    for (int cur = 0; cur < nv; cur++) {
        unsigned SC  = 0;
        unsigned SRm = ((cur & 31) == lane) ? (1u << (cur >> 5)) : 0u;
        #pragma unroll
        for (int k = 0; k < 8; k++) {
            spm[k] = ENC_INF;
            scv[k] = 0.0f;
            r4cr[k] = s_r4c[k * 32 + lane];   // snapshot (constant this run)
        }

        int   i  = cur;
        float mv = 0.0f;                 // minVal
        int   sink;

        // ---------------- Dijkstra ----------------
        for (;;) {
            const float ucur = s_u[i];
            float cv[8];
            if (i < RROWS) {
                const float* __restrict__ r = s_cost + i * NN;
                #pragma unroll
                for (int k = 0; k < 8; k++) cv[k] = r[k * 32 + lane];
            } else {
                const float* __restrict__ r = C + i * NN;
                #pragma unroll
                for (int k = 0; k < 8; k++) cv[k] = __ldg(r + k * 32 + lane);
            }

            // relax (reference FP order) in encoded domain, unpredicated:
            // em = SC ? UMAX : enc(rr); spm via IMNMX (no pred on chain).
            #pragma unroll
            for (int k = 0; k < 8; k++) {
                const float rr = ((mv + cv[k]) - ucur) - v[k];
                const unsigned e  = enc_f(rr);
                const unsigned em = ((SC >> k) & 1u) ? 0xFFFFFFFFu : e;
                if (em < spm[k]) path[k] = i;     // off-chain bookkeeping
                spm[k] = min(spm[k], em);
            }

            // local min via integer min tree (order-isomorphic to float min)
            const unsigned m01 = min(spm[0], spm[1]);
            const unsigned m23 = min(spm[2], spm[3]);
            const unsigned m45 = min(spm[4], spm[5]);
            const unsigned m67 = min(spm[6], spm[7]);
            const unsigned mloc = min(min(m01, m23), min(m45, m67));

            const unsigned mOrd = __reduce_min_sync(FULLM, mloc);

            // off-chain: lowest-k tied index + its row4col
            unsigned bits = 0;
            #pragma unroll
            for (int k = 0; k < 8; k++)
                if (spm[k] == mloc) bits |= 1u << k;
            const unsigned oneh = bits & (unsigned)(-(int)bits);
            int nxtl1 = 0;
            #pragma unroll
            for (int k = 0; k < 8; k++)
                nxtl1 += (int)((oneh >> k) & 1u) * (r4cr[k] + 1);
            const int kf = __ffs(bits) - 1;
            const unsigned bestIdx = (unsigned)(kf * 32 + lane);

            // branchless candidate: winners (mloc==mOrd) keep pack <= 0x1FFFF,
            // losers get +0x20000; REDUX-min = exact lowest-index tie-break,
            // winner carries next row for free
            const unsigned pack = (bestIdx << 9) | (unsigned)nxtl1;
            const unsigned cand = pack + (min(mloc - mOrd, 1u) << 17);
            const unsigned cw = __reduce_min_sync(FULLM, cand);
            const int jmin = (int)((cw >> 9) & 255u);
            const int nxt  = (int)(cw & 511u) - 1;

            mv = dec_f(mOrd);            // hides under REDUX2

            if ((jmin & 31) == lane) {
                const int kk = jmin >> 5;
                SC |= 1u << kk;
                scv[kk] = mv;            // frozen sp of this column == mv
                spm[kk] = 0xFFFFFFFFu;
            }
            if (nxt < 0) { sink = jmin; break; }
            i = nxt;
            if ((nxt & 31) == lane) SRm |= 1u << (nxt >> 5);
        }

        // write back sp + path for the random-access phases.
        // SC columns: frozen sp = scv (mv at SC-entry); others: dec(spm).
        float sp[8];
        #pragma unroll
        for (int k = 0; k < 8; k++) {
            const int idx = k * 32 + lane;
            sp[k] = ((SC >> k) & 1u) ? scv[k] : dec_f(spm[k]);
            s_sp[idx]   = sp[k];
            s_path[idx] = path[k];
        }
        __syncwarp();

        // ---------------- dual potential updates ----------------
        #pragma unroll
        for (int k = 0; k < 8; k++) {
            const int rrow = k * 32 + lane;
            if ((SRm >> k) & 1u) {
                int cc = s_c4r[rrow];
                cc = (cc < 0) ? 0 : ((cc > NN - 1) ? NN - 1 : cc);  // ref clip
                const float du = (rrow == cur) ? mv : (mv - s_sp[cc]);
                s_u[rrow] += du;
            }
            if ((SC >> k) & 1u) v[k] -= (mv - sp[k]);
        }
        __syncwarp();

        // ---------------- augment along alternating path ----------------
        if (lane == 0) {
            int j = sink;
            for (;;) {
                const int pi = s_path[j];
                s_r4c[j] = pi;
                const int jn = s_c4r[pi];
                s_c4r[pi] = j;
                if (pi == cur) break;
                j = jn;
            }
        }
        __syncwarp();
    }

    // ---------------- write output (float32 values) ----------------
    #pragma unroll
    for (int k = 0; k < 8; k++) {
        const int r = k * 32 + lane;
        if (r < nv) {
            int c = s_c4r[r];
            c = (c < 0) ? 0 : ((c > NN - 1) ? NN - 1 : c);
            out[b * NN + r] = (float)c;
        }
    }
    __syncwarp();
    if (lane == 0) {
        int pos = nv;
        for (int j = 0; j < NN; j++) {
            if (s_r4c[j] < 0 && pos < NN) out[b * NN + pos++] = (float)j;
        }
    }
}

// ---------------------------------------------------------------------------
extern "C" void kernel_launch(void* const* d_in, const int* in_sizes, int n_in,
                              void* d_out, int out_size) {
    const void* costs = d_in[0];
    const void* mask  = (n_in > 1) ? d_in[1] : d_in[0];
    for (int i = 0; i < n_in; i++) {
        if (in_sizes[i] == NB * NN * NN) costs = d_in[i];
        else if (in_sizes[i] == NB * NN) mask = d_in[i];
    }
    float* out = (float*)d_out;

    cudaFuncSetAttribute(lap_kernel,
                         cudaFuncAttributeMaxDynamicSharedMemorySize,
                         SMEM_BYTES);

    transpose_kernel<<<dim3(NN / 32, NN / 32, NB), dim3(32, 8)>>>(costs);
    lap_kernel<<<NB, 32, SMEM_BYTES>>>(mask, out);
}